// round 10
// baseline (speedup 1.0000x reference)
#include <cuda_runtime.h>
#include <cuda_bf16.h>
#include <cstdint>

#define BT_   8192
#define C_    1024
#define S_    4096
#define QH_   4
#define EPS_  1e-5f
#define NSPLIT 4
#define SSEG  1024            // S per split

// ---------------- scratch ----------------
__device__ __nv_bfloat16 g_q[(size_t)BT_ * 2048];   // 32MB [row][h*512 + (hi|lo)*256 + d]
__device__ __nv_bfloat16 g_k[(size_t)S_ * 512];     //  4MB [s][(hi|lo)*256 + d]
__device__ __nv_bfloat16 g_vt[2ull * 256 * S_];     //  4MB [hilo][d][s]
__device__ float g_part[(size_t)NSPLIT * BT_ * C_]; // 134MB partial outputs

// ---------------- helpers ----------------
__device__ __forceinline__ uint32_t smem_u32(const void* p) {
    uint32_t a;
    asm("{ .reg .u64 t; cvta.to.shared.u64 t, %1; cvt.u32.u64 %0, t; }" : "=r"(a) : "l"(p));
    return a;
}
#define CPA16(saddr, gptr) \
    asm volatile("cp.async.cg.shared.global [%0], [%1], 16;" :: "r"(saddr), "l"(gptr))
#define CPCOMMIT() asm volatile("cp.async.commit_group;" ::: "memory")
#define CPWAIT(n)  asm volatile("cp.async.wait_group " #n ";" ::: "memory")

__device__ __forceinline__ void ldsm4(uint32_t* r, uint32_t addr) {
    asm volatile("ldmatrix.sync.aligned.m8n8.x4.shared.b16 {%0,%1,%2,%3}, [%4];"
                 : "=r"(r[0]), "=r"(r[1]), "=r"(r[2]), "=r"(r[3]) : "r"(addr));
}
__device__ __forceinline__ void mma16816(float* c, const uint32_t* a, const uint32_t* b) {
    asm volatile("mma.sync.aligned.m16n8k16.row.col.f32.bf16.bf16.f32 "
                 "{%0,%1,%2,%3}, {%4,%5,%6,%7}, {%8,%9}, {%0,%1,%2,%3};"
                 : "+f"(c[0]), "+f"(c[1]), "+f"(c[2]), "+f"(c[3])
                 : "r"(a[0]), "r"(a[1]), "r"(a[2]), "r"(a[3]), "r"(b[0]), "r"(b[1]));
}
// pack (f0 -> low half, f1 -> high half)
__device__ __forceinline__ uint32_t pack_bf2(float f0, float f1) {
    uint32_t d;
    asm("cvt.rn.bf16x2.f32 %0, %1, %2;" : "=r"(d) : "f"(f1), "f"(f0));
    return d;
}
__device__ __forceinline__ void bf16_split(float v, __nv_bfloat16& hi, __nv_bfloat16& lo) {
    hi = __float2bfloat16(v);
    lo = __float2bfloat16(v - __bfloat162float(hi));
}

// ---------------------------------------------------------------------------
// LayerNorm + bf16 split -> g_q
// ---------------------------------------------------------------------------
__global__ void __launch_bounds__(256) ln_kernel(const float* __restrict__ res,
                                                 const float* __restrict__ gam,
                                                 const float* __restrict__ bet) {
    const int row = blockIdx.x;
    const float* x = res + (size_t)row * C_;
    const int t = threadIdx.x;

    float v[4];
    float s = 0.f;
#pragma unroll
    for (int i = 0; i < 4; i++) { v[i] = x[t + 256 * i]; s += v[i]; }

    __shared__ float red[8];
    __shared__ float sh_mu, sh_rs;
#pragma unroll
    for (int o = 16; o; o >>= 1) s += __shfl_xor_sync(0xffffffffu, s, o);
    if ((t & 31) == 0) red[t >> 5] = s;
    __syncthreads();
    if (t == 0) {
        float tot = 0.f;
#pragma unroll
        for (int i = 0; i < 8; i++) tot += red[i];
        sh_mu = tot * (1.0f / (float)C_);
    }
    __syncthreads();
    const float mu = sh_mu;
    float s2 = 0.f;
#pragma unroll
    for (int i = 0; i < 4; i++) { float d = v[i] - mu; s2 += d * d; }
#pragma unroll
    for (int o = 16; o; o >>= 1) s2 += __shfl_xor_sync(0xffffffffu, s2, o);
    if ((t & 31) == 0) red[t >> 5] = s2;
    __syncthreads();
    if (t == 0) {
        float tot = 0.f;
#pragma unroll
        for (int i = 0; i < 8; i++) tot += red[i];
        sh_rs = rsqrtf(tot * (1.0f / (float)C_) + EPS_);
    }
    __syncthreads();
    const float rs = sh_rs;

#pragma unroll
    for (int i = 0; i < 4; i++) {
        int c = t + 256 * i;
        float y = (v[i] - mu) * rs * gam[c] + bet[c];
        int h = c >> 8, d = c & 255;
        __nv_bfloat16 hi, lo;
        bf16_split(y, hi, lo);
        size_t base = (size_t)row * 2048 + h * 512 + d;
        g_q[base] = hi;
        g_q[base + 256] = lo;
    }
}

__global__ void __launch_bounds__(256) kext_kernel(const float* __restrict__ wfc) {
    int idx = blockIdx.x * 256 + threadIdx.x;
    float v = wfc[idx];
    int s = idx >> 8, d = idx & 255;
    __nv_bfloat16 hi, lo;
    bf16_split(v, hi, lo);
    g_k[(size_t)s * 512 + d] = hi;
    g_k[(size_t)s * 512 + 256 + d] = lo;
}

__global__ void __launch_bounds__(256) vext_kernel(const float* __restrict__ wproj) {
    int idx = blockIdx.x * 256 + threadIdx.x;
    float v = wproj[idx];
    int r = idx >> 10, cc = idx & 1023;
    int d = r & 255;
    int s = cc * 4 + (r >> 8);
    __nv_bfloat16 hi, lo;
    bf16_split(v, hi, lo);
    g_vt[(size_t)d * 4096 + s] = hi;
    g_vt[1048576ull + (size_t)d * 4096 + s] = lo;
}

// ---------------------------------------------------------------------------
// Reduce: out = residual + sum of 4 partials
// ---------------------------------------------------------------------------
__global__ void __launch_bounds__(256) reduce_kernel(const float* __restrict__ res,
                                                     float* __restrict__ out) {
    const size_t i = ((size_t)blockIdx.x * 256 + threadIdx.x) * 4;
    float4 a = *(const float4*)(res + i);
    float4 p0 = *(const float4*)(g_part + i);
    float4 p1 = *(const float4*)(g_part + (size_t)BT_ * C_ + i);
    float4 p2 = *(const float4*)(g_part + 2ull * BT_ * C_ + i);
    float4 p3 = *(const float4*)(g_part + 3ull * BT_ * C_ + i);
    float4 o;
    o.x = a.x + (p0.x + p1.x) + (p2.x + p3.x);
    o.y = a.y + (p0.y + p1.y) + (p2.y + p3.y);
    o.z = a.z + (p0.z + p1.z) + (p2.z + p3.z);
    o.w = a.w + (p0.w + p1.w) + (p2.w + p3.w);
    *(float4*)(out + i) = o;
}

// ---------------------------------------------------------------------------
// Fused kernel: CTA = 128 rows x 1 head x 1 S-split(1024); chunks of 32.
// 512 threads / 16 warps (4 per SMSP) to fill HMMA issue gaps.
// GEMM1 warp tile 16m x 16s (8x2). GEMM2 warp tile 32m x 64d (4x4).
// ---------------------------------------------------------------------------
#define SQ_OFF   0            // 128*1040   = 133120
#define SP_OFF   133120       // 2*128*80   = 20480
#define SP_LO    10240
#define SK_OFF   153600       // 32*1040    = 33280
#define SV_OFF   186880       // 2*256*80   = 40960
#define SV_LO    20480
#define SMEM_TOT 227840
#define NIT      (SSEG / 32)  // 32 chunks per split

__global__ void __launch_bounds__(512, 1) fused_kernel() {
    extern __shared__ char smem[];
    const uint32_t sb = smem_u32(smem);

    const int t = threadIdx.x;
    const int lane = t & 31;
    const int wid = t >> 5;         // 0..15
    const int r = lane >> 2;        // 0..7
    const int u = lane & 3;         // 0..3
    const int head = blockIdx.y;
    const int row0 = blockIdx.x * 128;
    const int sBase = blockIdx.z * SSEG;

    // GEMM1 warp coords: 8 m-groups x 2 s-halves
    const int my = wid >> 1;        // 0..7
    const int sx = wid & 1;         // 0..1
    // GEMM2 warp coords: 4 m-quarters x 4 d-quarters
    const int mq = wid & 3;         // 0..3
    const int dq = wid >> 2;        // 0..3

    // ---- issue Q (group), K(0) (group), V(0) (group) ----
#pragma unroll
    for (int i = 0; i < 16; i++) {
        int idx = i * 512 + t;
        int m = idx >> 6, c = idx & 63;
        CPA16(sb + SQ_OFF + m * 1040 + c * 16,
              (const void*)(g_q + (size_t)(row0 + m) * 2048 + head * 512 + c * 8));
    }
    CPCOMMIT();
#pragma unroll
    for (int i = 0; i < 4; i++) {
        int idx = i * 512 + t;
        int s = idx >> 6, c = idx & 63;
        CPA16(sb + SK_OFF + s * 1040 + c * 16,
              (const void*)(g_k + (size_t)(sBase + s) * 512 + c * 8));
    }
    CPCOMMIT();
#pragma unroll
    for (int i = 0; i < 4; i++) {
        int idx = i * 512 + t;
        int hilo = idx >> 10;
        int rem = idx & 1023;
        int d = rem >> 2, c = rem & 3;
        CPA16(sb + SV_OFF + hilo * SV_LO + d * 80 + c * 16,
              (const void*)(g_vt + (size_t)hilo * 1048576ull + (size_t)d * 4096 + sBase + c * 8));
    }
    CPCOMMIT();
    CPWAIT(1);              // Q + K(0) complete; V(0) pending
    __syncthreads();

    // ldmatrix lane addressing
    const uint32_t qa = sb + SQ_OFF + (uint32_t)((my * 16 + (lane & 15)) * 1040 + (lane >> 4) * 16);
    const int brow = (lane & 7) + ((lane >> 4) << 3);
    const int bc8  = ((lane >> 3) & 1) << 3;
    const uint32_t kb = sb + SK_OFF + (uint32_t)((sx * 16 + brow) * 1040 + bc8 * 2);
    const uint32_t pa = sb + SP_OFF + (uint32_t)((mq * 32 + (lane & 15)) * 80 + (lane >> 4) * 16);
    const uint32_t vb = sb + SV_OFF + (uint32_t)((dq * 64 + brow) * 80 + bc8 * 2);
    const uint32_t pw = sb + SP_OFF + (uint32_t)((my * 16 + r) * 80 + (sx * 16 + 2 * u) * 2);

    float c2[2][8][4];
#pragma unroll
    for (int a = 0; a < 2; a++)
#pragma unroll
        for (int b = 0; b < 8; b++)
#pragma unroll
            for (int e = 0; e < 4; e++) c2[a][b][e] = 0.f;

    for (int it = 0; it < NIT; it++) {
        // ---- GEMM1: scores[128 x 32]  (K(it) visible) ----
        float c1[2][4];
#pragma unroll
        for (int b = 0; b < 2; b++)
#pragma unroll
            for (int e = 0; e < 4; e++) c1[b][e] = 0.f;

#pragma unroll 8
        for (int ks = 0; ks < 16; ks++) {
            uint32_t ah[4], al[4], bh[4], bl[4];
            ldsm4(ah, qa + ks * 32);
            ldsm4(al, qa + 512 + ks * 32);
            ldsm4(bh, kb + ks * 32);
            ldsm4(bl, kb + 512 + ks * 32);
            mma16816(c1[0], ah, bh);  mma16816(c1[1], ah, bh + 2);
            mma16816(c1[0], ah, bl);  mma16816(c1[1], ah, bl + 2);
            mma16816(c1[0], al, bh);  mma16816(c1[1], al, bh + 2);
        }
        __syncthreads();        // sync_a: K buffer free

        // issue K(it+1)
        if (it < NIT - 1) {
            const int sn = sBase + (it + 1) * 32;
#pragma unroll
            for (int i = 0; i < 4; i++) {
                int idx = i * 512 + t;
                int s = idx >> 6, c = idx & 63;
                CPA16(sb + SK_OFF + s * 1040 + c * 16,
                      (const void*)(g_k + (size_t)(sn + s) * 512 + c * 8));
            }
            CPCOMMIT();
        }

        // ---- relu^2 + split -> P smem (overlaps K load) ----
#pragma unroll
        for (int nt = 0; nt < 2; nt++) {
            uint32_t base = pw + (uint32_t)(nt * 16);
#pragma unroll
            for (int half = 0; half < 2; half++) {
                float p0 = fmaxf(c1[nt][half * 2], 0.f);
                float p1 = fmaxf(c1[nt][half * 2 + 1], 0.f);
                p0 *= p0; p1 *= p1;
                uint32_t hh = pack_bf2(p0, p1);
                float h0 = __uint_as_float(hh << 16);
                float h1 = __uint_as_float(hh & 0xffff0000u);
                uint32_t ll = pack_bf2(p0 - h0, p1 - h1);
                uint32_t a = base + half * (8 * 80);
                *(uint32_t*)(smem + (a - sb)) = hh;
                *(uint32_t*)(smem + (a - sb) + SP_LO) = ll;
            }
        }

        if (it < NIT - 1) { CPWAIT(1); } else { CPWAIT(0); }   // V(it) complete
        __syncthreads();        // sync_b: P + V visible

        // ---- GEMM2: O[128 x 256] += P . V^T ----
#pragma unroll
        for (int ks = 0; ks < 2; ks++) {
            uint32_t Ph[2][4], Pl[2][4];
#pragma unroll
            for (int mt = 0; mt < 2; mt++) {
                ldsm4(Ph[mt], pa + (uint32_t)(mt * 16 * 80 + ks * 32));
                ldsm4(Pl[mt], pa + (uint32_t)(SP_LO + mt * 16 * 80 + ks * 32));
            }
#pragma unroll
            for (int h = 0; h < 4; h++) {
                uint32_t vh[4], vl[4];
                ldsm4(vh, vb + (uint32_t)(h * 16 * 80 + ks * 32));
                ldsm4(vl, vb + (uint32_t)(SV_LO + h * 16 * 80 + ks * 32));
#pragma unroll
                for (int mt = 0; mt < 2; mt++) {
                    float* cA = c2[mt][2 * h];
                    float* cB = c2[mt][2 * h + 1];
                    mma16816(cA, Ph[mt], vh);  mma16816(cB, Ph[mt], vh + 2);
                    mma16816(cA, Ph[mt], vl);  mma16816(cB, Ph[mt], vl + 2);
                    mma16816(cA, Pl[mt], vh);  mma16816(cB, Pl[mt], vh + 2);
                }
            }
        }

        CPWAIT(0);              // K(it+1) complete
        __syncthreads();        // sync_c: V,P free; K visible

        // issue V(it+1)
        if (it < NIT - 1) {
            const int sv = sBase + (it + 1) * 32;
#pragma unroll
            for (int i = 0; i < 4; i++) {
                int idx = i * 512 + t;
                int hilo = idx >> 10;
                int rem = idx & 1023;
                int d = rem >> 2, c = rem & 3;
                CPA16(sb + SV_OFF + hilo * SV_LO + d * 80 + c * 16,
                      (const void*)(g_vt + (size_t)hilo * 1048576ull +
                                    (size_t)d * 4096 + sv + c * 8));
            }
            CPCOMMIT();
        }
    }

    // ---- epilogue: write partial O (no residual) ----
    float* po = g_part + (size_t)blockIdx.z * BT_ * C_;
#pragma unroll
    for (int mt = 0; mt < 2; mt++) {
        const int rowA = row0 + mq * 32 + mt * 16 + r;
        const int rowB = rowA + 8;
        float* oA = po + (size_t)rowA * C_ + head * 256;
        float* oB = po + (size_t)rowB * C_ + head * 256;
#pragma unroll
        for (int j = 0; j < 8; j++) {
            const int col = dq * 64 + (j >> 1) * 16 + (j & 1) * 8 + 2 * u;
            *(float2*)(oA + col) = make_float2(c2[mt][j][0], c2[mt][j][1]);
            *(float2*)(oB + col) = make_float2(c2[mt][j][2], c2[mt][j][3]);
        }
    }
}

// ---------------------------------------------------------------------------
extern "C" void kernel_launch(void* const* d_in, const int* in_sizes, int n_in,
                              void* d_out, int out_size) {
    (void)in_sizes; (void)n_in; (void)out_size;
    const float* residual = (const float*)d_in[0];
    const float* w_fc     = (const float*)d_in[1];
    const float* w_proj   = (const float*)d_in[2];
    const float* ln_g     = (const float*)d_in[3];
    const float* ln_b     = (const float*)d_in[4];
    float* out = (float*)d_out;

    cudaFuncSetAttribute(fused_kernel, cudaFuncAttributeMaxDynamicSharedMemorySize,
                         SMEM_TOT);

    ln_kernel<<<BT_, 256>>>(residual, ln_g, ln_b);
    kext_kernel<<<4096, 256>>>(w_fc);
    vext_kernel<<<4096, 256>>>(w_proj);
    fused_kernel<<<dim3(64, QH_, NSPLIT), 512, SMEM_TOT>>>();
    reduce_kernel<<<BT_ * C_ / 1024, 256>>>(residual, out);
}

// round 11
// speedup vs baseline: 1.2419x; 1.2419x over previous
#include <cuda_runtime.h>
#include <cuda_fp16.h>
#include <cstdint>

#define BT_   8192
#define C_    1024
#define S_    4096
#define QH_   4
#define EPS_  1e-5f
#define NSPLIT 4
#define SSEG  1024            // S per split

// ---------------- scratch ----------------
__device__ __half g_q[(size_t)BT_ * 2048];   // 32MB [row][h*512 + (hi|lo)*256 + d]
__device__ __half g_k[(size_t)S_ * 512];     //  4MB [s][(hi|lo)*256 + d]
__device__ __half g_vt[2ull * 256 * S_];     //  4MB [hilo][d][s]
__device__ float g_part[(size_t)NSPLIT * BT_ * C_]; // 134MB partial outputs

// ---------------- helpers ----------------
__device__ __forceinline__ uint32_t smem_u32(const void* p) {
    uint32_t a;
    asm("{ .reg .u64 t; cvta.to.shared.u64 t, %1; cvt.u32.u64 %0, t; }" : "=r"(a) : "l"(p));
    return a;
}
#define CPA16(saddr, gptr) \
    asm volatile("cp.async.cg.shared.global [%0], [%1], 16;" :: "r"(saddr), "l"(gptr))
#define CPCOMMIT() asm volatile("cp.async.commit_group;" ::: "memory")
#define CPWAIT(n)  asm volatile("cp.async.wait_group " #n ";" ::: "memory")

__device__ __forceinline__ void ldsm4(uint32_t* r, uint32_t addr) {
    asm volatile("ldmatrix.sync.aligned.m8n8.x4.shared.b16 {%0,%1,%2,%3}, [%4];"
                 : "=r"(r[0]), "=r"(r[1]), "=r"(r[2]), "=r"(r[3]) : "r"(addr));
}
__device__ __forceinline__ void mma16816(float* c, const uint32_t* a, const uint32_t* b) {
    asm volatile("mma.sync.aligned.m16n8k16.row.col.f32.f16.f16.f32 "
                 "{%0,%1,%2,%3}, {%4,%5,%6,%7}, {%8,%9}, {%0,%1,%2,%3};"
                 : "+f"(c[0]), "+f"(c[1]), "+f"(c[2]), "+f"(c[3])
                 : "r"(a[0]), "r"(a[1]), "r"(a[2]), "r"(a[3]), "r"(b[0]), "r"(b[1]));
}
// pack (f0 -> low half, f1 -> high half)
__device__ __forceinline__ uint32_t pack_h2(float f0, float f1) {
    __half2 h = __floats2half2_rn(f0, f1);
    return *reinterpret_cast<uint32_t*>(&h);
}
__device__ __forceinline__ void fp16_split(float v, __half& hi, __half& lo) {
    hi = __float2half(v);
    lo = __float2half(v - __half2float(hi));
}

// ---------------------------------------------------------------------------
// LayerNorm + fp16 split -> g_q
// ---------------------------------------------------------------------------
__global__ void __launch_bounds__(256) ln_kernel(const float* __restrict__ res,
                                                 const float* __restrict__ gam,
                                                 const float* __restrict__ bet) {
    const int row = blockIdx.x;
    const float* x = res + (size_t)row * C_;
    const int t = threadIdx.x;

    float v[4];
    float s = 0.f;
#pragma unroll
    for (int i = 0; i < 4; i++) { v[i] = x[t + 256 * i]; s += v[i]; }

    __shared__ float red[8];
    __shared__ float sh_mu, sh_rs;
#pragma unroll
    for (int o = 16; o; o >>= 1) s += __shfl_xor_sync(0xffffffffu, s, o);
    if ((t & 31) == 0) red[t >> 5] = s;
    __syncthreads();
    if (t == 0) {
        float tot = 0.f;
#pragma unroll
        for (int i = 0; i < 8; i++) tot += red[i];
        sh_mu = tot * (1.0f / (float)C_);
    }
    __syncthreads();
    const float mu = sh_mu;
    float s2 = 0.f;
#pragma unroll
    for (int i = 0; i < 4; i++) { float d = v[i] - mu; s2 += d * d; }
#pragma unroll
    for (int o = 16; o; o >>= 1) s2 += __shfl_xor_sync(0xffffffffu, s2, o);
    if ((t & 31) == 0) red[t >> 5] = s2;
    __syncthreads();
    if (t == 0) {
        float tot = 0.f;
#pragma unroll
        for (int i = 0; i < 8; i++) tot += red[i];
        sh_rs = rsqrtf(tot * (1.0f / (float)C_) + EPS_);
    }
    __syncthreads();
    const float rs = sh_rs;

#pragma unroll
    for (int i = 0; i < 4; i++) {
        int c = t + 256 * i;
        float y = (v[i] - mu) * rs * gam[c] + bet[c];
        int h = c >> 8, d = c & 255;
        __half hi, lo;
        fp16_split(y, hi, lo);
        size_t base = (size_t)row * 2048 + h * 512 + d;
        g_q[base] = hi;
        g_q[base + 256] = lo;
    }
}

__global__ void __launch_bounds__(256) kext_kernel(const float* __restrict__ wfc) {
    int idx = blockIdx.x * 256 + threadIdx.x;
    float v = wfc[idx];
    int s = idx >> 8, d = idx & 255;
    __half hi, lo;
    fp16_split(v, hi, lo);
    g_k[(size_t)s * 512 + d] = hi;
    g_k[(size_t)s * 512 + 256 + d] = lo;
}

__global__ void __launch_bounds__(256) vext_kernel(const float* __restrict__ wproj) {
    int idx = blockIdx.x * 256 + threadIdx.x;
    float v = wproj[idx];
    int r = idx >> 10, cc = idx & 1023;
    int d = r & 255;
    int s = cc * 4 + (r >> 8);
    __half hi, lo;
    fp16_split(v, hi, lo);
    g_vt[(size_t)d * 4096 + s] = hi;
    g_vt[1048576ull + (size_t)d * 4096 + s] = lo;
}

// ---------------------------------------------------------------------------
// Reduce: out = residual + sum of 4 partials
// ---------------------------------------------------------------------------
__global__ void __launch_bounds__(256) reduce_kernel(const float* __restrict__ res,
                                                     float* __restrict__ out) {
    const size_t i = ((size_t)blockIdx.x * 256 + threadIdx.x) * 4;
    float4 a = *(const float4*)(res + i);
    float4 p0 = *(const float4*)(g_part + i);
    float4 p1 = *(const float4*)(g_part + (size_t)BT_ * C_ + i);
    float4 p2 = *(const float4*)(g_part + 2ull * BT_ * C_ + i);
    float4 p3 = *(const float4*)(g_part + 3ull * BT_ * C_ + i);
    float4 o;
    o.x = a.x + (p0.x + p1.x) + (p2.x + p3.x);
    o.y = a.y + (p0.y + p1.y) + (p2.y + p3.y);
    o.z = a.z + (p0.z + p1.z) + (p2.z + p3.z);
    o.w = a.w + (p0.w + p1.w) + (p2.w + p3.w);
    *(float4*)(out + i) = o;
}

// ---------------------------------------------------------------------------
// Fused kernel: CTA = 128 rows x 1 head x 1 S-split(1024); chunks of 32.
// fp16 operands; GEMM1 3 split terms; GEMM2 2 terms (P unsplit fp16).
// GEMM1 warp tile 32m x 16s (4x2). GEMM2 warp tile 64m x 64d (2x4).
// ---------------------------------------------------------------------------
#define SQ_OFF   0            // 128*1040   = 133120
#define SP_OFF   133120       // 128*80     = 10240 (single, fp16 unsplit)
#define SK_OFF   143360       // 32*1040    = 33280
#define SV_OFF   176640       // 2*256*80   = 40960
#define SV_LO    20480
#define SMEM_TOT 217600
#define NIT      (SSEG / 32)  // 32 chunks per split

__global__ void __launch_bounds__(256, 1) fused_kernel() {
    extern __shared__ char smem[];
    const uint32_t sb = smem_u32(smem);

    const int t = threadIdx.x;
    const int lane = t & 31;
    const int wid = t >> 5;
    const int r = lane >> 2;        // 0..7
    const int u = lane & 3;         // 0..3
    const int head = blockIdx.y;
    const int row0 = blockIdx.x * 128;
    const int sBase = blockIdx.z * SSEG;

    // GEMM1 warp coords: 4 m-groups x 2 s-halves
    const int my = wid & 3;
    const int sx = wid >> 2;
    // GEMM2 warp coords: 2 m-halves x 4 d-quarters
    const int mh = wid & 1;
    const int dq = wid >> 1;

    // ---- issue Q (group), K(0) (group), V(0) (group) ----
#pragma unroll
    for (int i = 0; i < 32; i++) {
        int idx = i * 256 + t;
        int m = idx >> 6, c = idx & 63;
        CPA16(sb + SQ_OFF + m * 1040 + c * 16,
              (const void*)(g_q + (size_t)(row0 + m) * 2048 + head * 512 + c * 8));
    }
    CPCOMMIT();
#pragma unroll
    for (int i = 0; i < 8; i++) {
        int idx = i * 256 + t;
        int s = idx >> 6, c = idx & 63;
        CPA16(sb + SK_OFF + s * 1040 + c * 16,
              (const void*)(g_k + (size_t)(sBase + s) * 512 + c * 8));
    }
    CPCOMMIT();
#pragma unroll
    for (int i = 0; i < 8; i++) {
        int idx = i * 256 + t;
        int hilo = idx >> 10;
        int rem = idx & 1023;
        int d = rem >> 2, c = rem & 3;
        CPA16(sb + SV_OFF + hilo * SV_LO + d * 80 + c * 16,
              (const void*)(g_vt + (size_t)hilo * 1048576ull + (size_t)d * 4096 + sBase + c * 8));
    }
    CPCOMMIT();
    CPWAIT(1);              // Q + K(0) complete; V(0) pending
    __syncthreads();

    // ldmatrix lane addressing
    const uint32_t qa = sb + SQ_OFF + (uint32_t)((my * 32 + (lane & 15)) * 1040 + (lane >> 4) * 16);
    const int brow = (lane & 7) + ((lane >> 4) << 3);
    const int bc8  = ((lane >> 3) & 1) << 3;
    const uint32_t kb = sb + SK_OFF + (uint32_t)((sx * 16 + brow) * 1040 + bc8 * 2);
    const uint32_t pa = sb + SP_OFF + (uint32_t)((mh * 64 + (lane & 15)) * 80 + (lane >> 4) * 16);
    const uint32_t vb = sb + SV_OFF + (uint32_t)((dq * 64 + brow) * 80 + bc8 * 2);
    const uint32_t pw = sb + SP_OFF + (uint32_t)((my * 32 + r) * 80 + (sx * 16 + 2 * u) * 2);

    float c2[4][8][4];
#pragma unroll
    for (int a = 0; a < 4; a++)
#pragma unroll
        for (int b = 0; b < 8; b++)
#pragma unroll
            for (int e = 0; e < 4; e++) c2[a][b][e] = 0.f;

    for (int it = 0; it < NIT; it++) {
        // ---- GEMM1: scores[128 x 32]  (K(it) visible) ----
        float c1[2][2][4];
#pragma unroll
        for (int a = 0; a < 2; a++)
#pragma unroll
            for (int b = 0; b < 2; b++)
#pragma unroll
                for (int e = 0; e < 4; e++) c1[a][b][e] = 0.f;

#pragma unroll 8
        for (int ks = 0; ks < 16; ks++) {
            uint32_t ah0[4], ah1[4], al0[4], al1[4], bh[4], bl[4];
            ldsm4(ah0, qa + ks * 32);
            ldsm4(ah1, qa + 16 * 1040 + ks * 32);
            ldsm4(al0, qa + 512 + ks * 32);
            ldsm4(al1, qa + 16 * 1040 + 512 + ks * 32);
            ldsm4(bh, kb + ks * 32);
            ldsm4(bl, kb + 512 + ks * 32);
            mma16816(c1[0][0], ah0, bh);  mma16816(c1[0][1], ah0, bh + 2);
            mma16816(c1[1][0], ah1, bh);  mma16816(c1[1][1], ah1, bh + 2);
            mma16816(c1[0][0], ah0, bl);  mma16816(c1[0][1], ah0, bl + 2);
            mma16816(c1[1][0], ah1, bl);  mma16816(c1[1][1], ah1, bl + 2);
            mma16816(c1[0][0], al0, bh);  mma16816(c1[0][1], al0, bh + 2);
            mma16816(c1[1][0], al1, bh);  mma16816(c1[1][1], al1, bh + 2);
        }
        __syncthreads();        // sync_a: K buffer free

        // issue K(it+1)
        if (it < NIT - 1) {
            const int sn = sBase + (it + 1) * 32;
#pragma unroll
            for (int i = 0; i < 8; i++) {
                int idx = i * 256 + t;
                int s = idx >> 6, c = idx & 63;
                CPA16(sb + SK_OFF + s * 1040 + c * 16,
                      (const void*)(g_k + (size_t)(sn + s) * 512 + c * 8));
            }
            CPCOMMIT();
        }

        // ---- relu^2 -> P (unsplit fp16) smem (overlaps K load) ----
#pragma unroll
        for (int mt = 0; mt < 2; mt++) {
#pragma unroll
            for (int nt = 0; nt < 2; nt++) {
                uint32_t base = pw + (uint32_t)(mt * 16 * 80 + nt * 16);
#pragma unroll
                for (int half = 0; half < 2; half++) {
                    float p0 = fmaxf(c1[mt][nt][half * 2], 0.f);
                    float p1 = fmaxf(c1[mt][nt][half * 2 + 1], 0.f);
                    uint32_t a = base + half * (8 * 80);
                    *(uint32_t*)(smem + (a - sb)) = pack_h2(p0 * p0, p1 * p1);
                }
            }
        }

        if (it < NIT - 1) { CPWAIT(1); } else { CPWAIT(0); }   // V(it) complete
        __syncthreads();        // sync_b: P + V visible

        // ---- GEMM2: O[128 x 256] += P . (Vh + Vl)^T  (2 terms) ----
#pragma unroll
        for (int ks = 0; ks < 2; ks++) {
            uint32_t Ph[4][4];
#pragma unroll
            for (int mt = 0; mt < 4; mt++)
                ldsm4(Ph[mt], pa + (uint32_t)(mt * 16 * 80 + ks * 32));
#pragma unroll
            for (int h = 0; h < 4; h++) {
                uint32_t vh[4], vl[4];
                ldsm4(vh, vb + (uint32_t)(h * 16 * 80 + ks * 32));
                ldsm4(vl, vb + (uint32_t)(SV_LO + h * 16 * 80 + ks * 32));
#pragma unroll
                for (int mt = 0; mt < 4; mt++) {
                    float* cA = c2[mt][2 * h];
                    float* cB = c2[mt][2 * h + 1];
                    mma16816(cA, Ph[mt], vh);  mma16816(cB, Ph[mt], vh + 2);
                    mma16816(cA, Ph[mt], vl);  mma16816(cB, Ph[mt], vl + 2);
                }
            }
        }

        CPWAIT(0);              // K(it+1) complete
        __syncthreads();        // sync_c: V,P free; K visible

        // issue V(it+1)
        if (it < NIT - 1) {
            const int sv = sBase + (it + 1) * 32;
#pragma unroll
            for (int i = 0; i < 8; i++) {
                int idx = i * 256 + t;
                int hilo = idx >> 10;
                int rem = idx & 1023;
                int d = rem >> 2, c = rem & 3;
                CPA16(sb + SV_OFF + hilo * SV_LO + d * 80 + c * 16,
                      (const void*)(g_vt + (size_t)hilo * 1048576ull +
                                    (size_t)d * 4096 + sv + c * 8));
            }
            CPCOMMIT();
        }
    }

    // ---- epilogue: write partial O (no residual) ----
    float* po = g_part + (size_t)blockIdx.z * BT_ * C_;
#pragma unroll
    for (int mt = 0; mt < 4; mt++) {
        const int rowA = row0 + mh * 64 + mt * 16 + r;
        const int rowB = rowA + 8;
        float* oA = po + (size_t)rowA * C_ + head * 256;
        float* oB = po + (size_t)rowB * C_ + head * 256;
#pragma unroll
        for (int j = 0; j < 8; j++) {
            const int col = dq * 64 + (j >> 1) * 16 + (j & 1) * 8 + 2 * u;
            *(float2*)(oA + col) = make_float2(c2[mt][j][0], c2[mt][j][1]);
            *(float2*)(oB + col) = make_float2(c2[mt][j][2], c2[mt][j][3]);
        }
    }
}

// ---------------------------------------------------------------------------
extern "C" void kernel_launch(void* const* d_in, const int* in_sizes, int n_in,
                              void* d_out, int out_size) {
    (void)in_sizes; (void)n_in; (void)out_size;
    const float* residual = (const float*)d_in[0];
    const float* w_fc     = (const float*)d_in[1];
    const float* w_proj   = (const float*)d_in[2];
    const float* ln_g     = (const float*)d_in[3];
    const float* ln_b     = (const float*)d_in[4];
    float* out = (float*)d_out;

    cudaFuncSetAttribute(fused_kernel, cudaFuncAttributeMaxDynamicSharedMemorySize,
                         SMEM_TOT);

    ln_kernel<<<BT_, 256>>>(residual, ln_g, ln_b);
    kext_kernel<<<4096, 256>>>(w_fc);
    vext_kernel<<<4096, 256>>>(w_proj);
    fused_kernel<<<dim3(64, QH_, NSPLIT), 256, SMEM_TOT>>>();
    reduce_kernel<<<BT_ * C_ / 1024, 256>>>(residual, out);
}

// round 12
// speedup vs baseline: 1.4496x; 1.1673x over previous
#include <cuda_runtime.h>
#include <cuda_fp16.h>
#include <cstdint>

#define BT_   8192
#define C_    1024
#define S_    4096
#define QH_   4
#define EPS_  1e-5f
#define NSPLIT 4
#define SSEG  1024            // S per split

// ---------------- scratch ----------------
__device__ __half g_q[(size_t)BT_ * 1024];   // 16MB [row][h*256 + d] (hi only)
__device__ __half g_k[(size_t)S_ * 512];     //  4MB [s][(hi|lo)*256 + d]
__device__ __half g_vt[2ull * 256 * S_];     //  4MB [hilo][d][s]
__device__ float g_part[(size_t)NSPLIT * BT_ * C_]; // 134MB partial outputs

// ---------------- helpers ----------------
__device__ __forceinline__ uint32_t smem_u32(const void* p) {
    uint32_t a;
    asm("{ .reg .u64 t; cvta.to.shared.u64 t, %1; cvt.u32.u64 %0, t; }" : "=r"(a) : "l"(p));
    return a;
}
#define CPA16(saddr, gptr) \
    asm volatile("cp.async.cg.shared.global [%0], [%1], 16;" :: "r"(saddr), "l"(gptr))
#define CPCOMMIT() asm volatile("cp.async.commit_group;" ::: "memory")
#define CPWAIT(n)  asm volatile("cp.async.wait_group " #n ";" ::: "memory")

__device__ __forceinline__ void ldsm4(uint32_t* r, uint32_t addr) {
    asm volatile("ldmatrix.sync.aligned.m8n8.x4.shared.b16 {%0,%1,%2,%3}, [%4];"
                 : "=r"(r[0]), "=r"(r[1]), "=r"(r[2]), "=r"(r[3]) : "r"(addr));
}
__device__ __forceinline__ void mma16816(float* c, const uint32_t* a, const uint32_t* b) {
    asm volatile("mma.sync.aligned.m16n8k16.row.col.f32.f16.f16.f32 "
                 "{%0,%1,%2,%3}, {%4,%5,%6,%7}, {%8,%9}, {%0,%1,%2,%3};"
                 : "+f"(c[0]), "+f"(c[1]), "+f"(c[2]), "+f"(c[3])
                 : "r"(a[0]), "r"(a[1]), "r"(a[2]), "r"(a[3]), "r"(b[0]), "r"(b[1]));
}
__device__ __forceinline__ uint32_t pack_h2(float f0, float f1) {
    __half2 h = __floats2half2_rn(f0, f1);
    return *reinterpret_cast<uint32_t*>(&h);
}
__device__ __forceinline__ void fp16_split(float v, __half& hi, __half& lo) {
    hi = __float2half(v);
    lo = __float2half(v - __half2float(hi));
}

// ---------------------------------------------------------------------------
// LayerNorm -> g_q (fp16 hi only)
// ---------------------------------------------------------------------------
__global__ void __launch_bounds__(256) ln_kernel(const float* __restrict__ res,
                                                 const float* __restrict__ gam,
                                                 const float* __restrict__ bet) {
    const int row = blockIdx.x;
    const float* x = res + (size_t)row * C_;
    const int t = threadIdx.x;

    float v[4];
    float s = 0.f;
#pragma unroll
    for (int i = 0; i < 4; i++) { v[i] = x[t + 256 * i]; s += v[i]; }

    __shared__ float red[8];
    __shared__ float sh_mu, sh_rs;
#pragma unroll
    for (int o = 16; o; o >>= 1) s += __shfl_xor_sync(0xffffffffu, s, o);
    if ((t & 31) == 0) red[t >> 5] = s;
    __syncthreads();
    if (t == 0) {
        float tot = 0.f;
#pragma unroll
        for (int i = 0; i < 8; i++) tot += red[i];
        sh_mu = tot * (1.0f / (float)C_);
    }
    __syncthreads();
    const float mu = sh_mu;
    float s2 = 0.f;
#pragma unroll
    for (int i = 0; i < 4; i++) { float d = v[i] - mu; s2 += d * d; }
#pragma unroll
    for (int o = 16; o; o >>= 1) s2 += __shfl_xor_sync(0xffffffffu, s2, o);
    if ((t & 31) == 0) red[t >> 5] = s2;
    __syncthreads();
    if (t == 0) {
        float tot = 0.f;
#pragma unroll
        for (int i = 0; i < 8; i++) tot += red[i];
        sh_rs = rsqrtf(tot * (1.0f / (float)C_) + EPS_);
    }
    __syncthreads();
    const float rs = sh_rs;

#pragma unroll
    for (int i = 0; i < 4; i++) {
        int c = t + 256 * i;
        float y = (v[i] - mu) * rs * gam[c] + bet[c];
        g_q[(size_t)row * 1024 + c] = __float2half(y);
    }
}

__global__ void __launch_bounds__(256) kext_kernel(const float* __restrict__ wfc) {
    int idx = blockIdx.x * 256 + threadIdx.x;
    float v = wfc[idx];
    int s = idx >> 8, d = idx & 255;
    __half hi, lo;
    fp16_split(v, hi, lo);
    g_k[(size_t)s * 512 + d] = hi;
    g_k[(size_t)s * 512 + 256 + d] = lo;
}

__global__ void __launch_bounds__(256) vext_kernel(const float* __restrict__ wproj) {
    int idx = blockIdx.x * 256 + threadIdx.x;
    float v = wproj[idx];
    int r = idx >> 10, cc = idx & 1023;
    int d = r & 255;
    int s = cc * 4 + (r >> 8);
    __half hi, lo;
    fp16_split(v, hi, lo);
    g_vt[(size_t)d * 4096 + s] = hi;
    g_vt[1048576ull + (size_t)d * 4096 + s] = lo;
}

// ---------------------------------------------------------------------------
// Reduce: out = residual + sum of 4 partials
// ---------------------------------------------------------------------------
__global__ void __launch_bounds__(256) reduce_kernel(const float* __restrict__ res,
                                                     float* __restrict__ out) {
    const size_t i = ((size_t)blockIdx.x * 256 + threadIdx.x) * 4;
    float4 a = *(const float4*)(res + i);
    float4 p0 = *(const float4*)(g_part + i);
    float4 p1 = *(const float4*)(g_part + (size_t)BT_ * C_ + i);
    float4 p2 = *(const float4*)(g_part + 2ull * BT_ * C_ + i);
    float4 p3 = *(const float4*)(g_part + 3ull * BT_ * C_ + i);
    float4 o;
    o.x = a.x + (p0.x + p1.x) + (p2.x + p3.x);
    o.y = a.y + (p0.y + p1.y) + (p2.y + p3.y);
    o.z = a.z + (p0.z + p1.z) + (p2.z + p3.z);
    o.w = a.w + (p0.w + p1.w) + (p2.w + p3.w);
    *(float4*)(out + i) = o;
}

// ---------------------------------------------------------------------------
// Fused kernel: CTA = 128 rows x 1 head x 1 S-split(1024); chunks of 32.
// fp16; GEMM1 2 terms (Q unsplit, K split); GEMM2 2 terms (P unsplit, V split).
// GEMM1 warp tile 32m x 16s (4x2). GEMM2 warp tile 64m x 64d (2x4).
// ---------------------------------------------------------------------------
#define SQ_OFF   0            // 128*528    = 67584
#define SP_OFF   67584        // 128*80     = 10240
#define SK_OFF   77824        // 32*1040    = 33280
#define SV_OFF   111104       // 2*256*80   = 40960
#define SV_LO    20480
#define SMEM_TOT 152064
#define NIT      (SSEG / 32)  // 32 chunks per split

__global__ void __launch_bounds__(256, 1) fused_kernel() {
    extern __shared__ char smem[];
    const uint32_t sb = smem_u32(smem);

    const int t = threadIdx.x;
    const int lane = t & 31;
    const int wid = t >> 5;
    const int r = lane >> 2;        // 0..7
    const int u = lane & 3;         // 0..3
    const int head = blockIdx.y;
    const int row0 = blockIdx.x * 128;
    const int sBase = blockIdx.z * SSEG;

    // GEMM1 warp coords: 4 m-groups x 2 s-halves
    const int my = wid & 3;
    const int sx = wid >> 2;
    // GEMM2 warp coords: 2 m-halves x 4 d-quarters
    const int mh = wid & 1;
    const int dq = wid >> 1;

    // ---- issue Q (group), K(0) (group), V(0) (group) ----
#pragma unroll
    for (int i = 0; i < 16; i++) {
        int idx = i * 256 + t;
        int m = idx >> 5, c = idx & 31;
        CPA16(sb + SQ_OFF + m * 528 + c * 16,
              (const void*)(g_q + (size_t)(row0 + m) * 1024 + head * 256 + c * 8));
    }
    CPCOMMIT();
#pragma unroll
    for (int i = 0; i < 8; i++) {
        int idx = i * 256 + t;
        int s = idx >> 6, c = idx & 63;
        CPA16(sb + SK_OFF + s * 1040 + c * 16,
              (const void*)(g_k + (size_t)(sBase + s) * 512 + c * 8));
    }
    CPCOMMIT();
#pragma unroll
    for (int i = 0; i < 8; i++) {
        int idx = i * 256 + t;
        int hilo = idx >> 10;
        int rem = idx & 1023;
        int d = rem >> 2, c = rem & 3;
        CPA16(sb + SV_OFF + hilo * SV_LO + d * 80 + c * 16,
              (const void*)(g_vt + (size_t)hilo * 1048576ull + (size_t)d * 4096 + sBase + c * 8));
    }
    CPCOMMIT();
    CPWAIT(1);              // Q + K(0) complete; V(0) pending
    __syncthreads();

    // ldmatrix lane addressing
    const uint32_t qa = sb + SQ_OFF + (uint32_t)((my * 32 + (lane & 15)) * 528 + (lane >> 4) * 16);
    const int brow = (lane & 7) + ((lane >> 4) << 3);
    const int bc8  = ((lane >> 3) & 1) << 3;
    const uint32_t kb = sb + SK_OFF + (uint32_t)((sx * 16 + brow) * 1040 + bc8 * 2);
    const uint32_t pa = sb + SP_OFF + (uint32_t)((mh * 64 + (lane & 15)) * 80 + (lane >> 4) * 16);
    const uint32_t vb = sb + SV_OFF + (uint32_t)((dq * 64 + brow) * 80 + bc8 * 2);
    const uint32_t pw = sb + SP_OFF + (uint32_t)((my * 32 + r) * 80 + (sx * 16 + 2 * u) * 2);

    float c2[4][8][4];
#pragma unroll
    for (int a = 0; a < 4; a++)
#pragma unroll
        for (int b = 0; b < 8; b++)
#pragma unroll
            for (int e = 0; e < 4; e++) c2[a][b][e] = 0.f;

    for (int it = 0; it < NIT; it++) {
        // ---- GEMM1: scores[128 x 32]  (K(it) visible) ----
        float c1[2][2][4];
#pragma unroll
        for (int a = 0; a < 2; a++)
#pragma unroll
            for (int b = 0; b < 2; b++)
#pragma unroll
                for (int e = 0; e < 4; e++) c1[a][b][e] = 0.f;

#pragma unroll 8
        for (int ks = 0; ks < 16; ks++) {
            uint32_t ah0[4], ah1[4], bh[4], bl[4];
            ldsm4(ah0, qa + ks * 32);
            ldsm4(ah1, qa + 16 * 528 + ks * 32);
            ldsm4(bh, kb + ks * 32);
            ldsm4(bl, kb + 512 + ks * 32);
            mma16816(c1[0][0], ah0, bh);  mma16816(c1[0][1], ah0, bh + 2);
            mma16816(c1[1][0], ah1, bh);  mma16816(c1[1][1], ah1, bh + 2);
            mma16816(c1[0][0], ah0, bl);  mma16816(c1[0][1], ah0, bl + 2);
            mma16816(c1[1][0], ah1, bl);  mma16816(c1[1][1], ah1, bl + 2);
        }
        __syncthreads();        // sync_a: K buffer free

        // issue K(it+1)
        if (it < NIT - 1) {
            const int sn = sBase + (it + 1) * 32;
#pragma unroll
            for (int i = 0; i < 8; i++) {
                int idx = i * 256 + t;
                int s = idx >> 6, c = idx & 63;
                CPA16(sb + SK_OFF + s * 1040 + c * 16,
                      (const void*)(g_k + (size_t)(sn + s) * 512 + c * 8));
            }
            CPCOMMIT();
        }

        // ---- relu^2 -> P (unsplit fp16) smem (overlaps K load) ----
#pragma unroll
        for (int mt = 0; mt < 2; mt++) {
#pragma unroll
            for (int nt = 0; nt < 2; nt++) {
                uint32_t base = pw + (uint32_t)(mt * 16 * 80 + nt * 16);
#pragma unroll
                for (int half = 0; half < 2; half++) {
                    float p0 = fmaxf(c1[mt][nt][half * 2], 0.f);
                    float p1 = fmaxf(c1[mt][nt][half * 2 + 1], 0.f);
                    uint32_t a = base + half * (8 * 80);
                    *(uint32_t*)(smem + (a - sb)) = pack_h2(p0 * p0, p1 * p1);
                }
            }
        }

        if (it < NIT - 1) { CPWAIT(1); } else { CPWAIT(0); }   // V(it) complete
        __syncthreads();        // sync_b: P + V visible

        // ---- GEMM2: O[128 x 256] += P . (Vh + Vl)^T  (2 terms) ----
#pragma unroll
        for (int ks = 0; ks < 2; ks++) {
            uint32_t Ph[4][4];
#pragma unroll
            for (int mt = 0; mt < 4; mt++)
                ldsm4(Ph[mt], pa + (uint32_t)(mt * 16 * 80 + ks * 32));
#pragma unroll
            for (int h = 0; h < 4; h++) {
                uint32_t vh[4], vl[4];
                ldsm4(vh, vb + (uint32_t)(h * 16 * 80 + ks * 32));
                ldsm4(vl, vb + (uint32_t)(SV_LO + h * 16 * 80 + ks * 32));
#pragma unroll
                for (int mt = 0; mt < 4; mt++) {
                    float* cA = c2[mt][2 * h];
                    float* cB = c2[mt][2 * h + 1];
                    mma16816(cA, Ph[mt], vh);  mma16816(cB, Ph[mt], vh + 2);
                    mma16816(cA, Ph[mt], vl);  mma16816(cB, Ph[mt], vl + 2);
                }
            }
        }

        CPWAIT(0);              // K(it+1) complete
        __syncthreads();        // sync_c: V,P free; K visible

        // issue V(it+1)
        if (it < NIT - 1) {
            const int sv = sBase + (it + 1) * 32;
#pragma unroll
            for (int i = 0; i < 8; i++) {
                int idx = i * 256 + t;
                int hilo = idx >> 10;
                int rem = idx & 1023;
                int d = rem >> 2, c = rem & 3;
                CPA16(sb + SV_OFF + hilo * SV_LO + d * 80 + c * 16,
                      (const void*)(g_vt + (size_t)hilo * 1048576ull +
                                    (size_t)d * 4096 + sv + c * 8));
            }
            CPCOMMIT();
        }
    }

    // ---- epilogue: write partial O (no residual) ----
    float* po = g_part + (size_t)blockIdx.z * BT_ * C_;
#pragma unroll
    for (int mt = 0; mt < 4; mt++) {
        const int rowA = row0 + mh * 64 + mt * 16 + r;
        const int rowB = rowA + 8;
        float* oA = po + (size_t)rowA * C_ + head * 256;
        float* oB = po + (size_t)rowB * C_ + head * 256;
#pragma unroll
        for (int j = 0; j < 8; j++) {
            const int col = dq * 64 + (j >> 1) * 16 + (j & 1) * 8 + 2 * u;
            *(float2*)(oA + col) = make_float2(c2[mt][j][0], c2[mt][j][1]);
            *(float2*)(oB + col) = make_float2(c2[mt][j][2], c2[mt][j][3]);
        }
    }
}

// ---------------------------------------------------------------------------
extern "C" void kernel_launch(void* const* d_in, const int* in_sizes, int n_in,
                              void* d_out, int out_size) {
    (void)in_sizes; (void)n_in; (void)out_size;
    const float* residual = (const float*)d_in[0];
    const float* w_fc     = (const float*)d_in[1];
    const float* w_proj   = (const float*)d_in[2];
    const float* ln_g     = (const float*)d_in[3];
    const float* ln_b     = (const float*)d_in[4];
    float* out = (float*)d_out;

    cudaFuncSetAttribute(fused_kernel, cudaFuncAttributeMaxDynamicSharedMemorySize,
                         SMEM_TOT);

    ln_kernel<<<BT_, 256>>>(residual, ln_g, ln_b);
    kext_kernel<<<4096, 256>>>(w_fc);
    vext_kernel<<<4096, 256>>>(w_proj);
    fused_kernel<<<dim3(64, QH_, NSPLIT), 256, SMEM_TOT>>>();
    reduce_kernel<<<BT_ * C_ / 1024, 256>>>(residual, out);
}

// round 13
// speedup vs baseline: 1.6024x; 1.1054x over previous
#include <cuda_runtime.h>
#include <cuda_fp16.h>
#include <cstdint>

#define BT_   8192
#define C_    1024
#define S_    4096
#define QH_   4
#define EPS_  1e-5f
#define NSPLIT 4
#define SSEG  1024            // S per split

// ---------------- scratch ----------------
__device__ __half g_q[(size_t)BT_ * 1024];   // 16MB [row][h*256 + d] (hi only)
__device__ __half g_k[(size_t)S_ * 512];     //  4MB [s][(hi|lo)*256 + d]
__device__ __half g_vt[2ull * 256 * S_];     //  4MB [hilo][d][s]
__device__ float g_part[(size_t)NSPLIT * BT_ * C_]; // 134MB partial outputs

// ---------------- helpers ----------------
__device__ __forceinline__ uint32_t smem_u32(const void* p) {
    uint32_t a;
    asm("{ .reg .u64 t; cvta.to.shared.u64 t, %1; cvt.u32.u64 %0, t; }" : "=r"(a) : "l"(p));
    return a;
}
#define CPA16(saddr, gptr) \
    asm volatile("cp.async.cg.shared.global [%0], [%1], 16;" :: "r"(saddr), "l"(gptr))
#define CPCOMMIT() asm volatile("cp.async.commit_group;" ::: "memory")
#define CPWAIT(n)  asm volatile("cp.async.wait_group " #n ";" ::: "memory")

__device__ __forceinline__ void ldsm4(uint32_t* r, uint32_t addr) {
    asm volatile("ldmatrix.sync.aligned.m8n8.x4.shared.b16 {%0,%1,%2,%3}, [%4];"
                 : "=r"(r[0]), "=r"(r[1]), "=r"(r[2]), "=r"(r[3]) : "r"(addr));
}
__device__ __forceinline__ void mma16816(float* c, const uint32_t* a, const uint32_t* b) {
    asm volatile("mma.sync.aligned.m16n8k16.row.col.f32.f16.f16.f32 "
                 "{%0,%1,%2,%3}, {%4,%5,%6,%7}, {%8,%9}, {%0,%1,%2,%3};"
                 : "+f"(c[0]), "+f"(c[1]), "+f"(c[2]), "+f"(c[3])
                 : "r"(a[0]), "r"(a[1]), "r"(a[2]), "r"(a[3]), "r"(b[0]), "r"(b[1]));
}
__device__ __forceinline__ uint32_t pack_h2(float f0, float f1) {
    __half2 h = __floats2half2_rn(f0, f1);
    return *reinterpret_cast<uint32_t*>(&h);
}
__device__ __forceinline__ void fp16_split(float v, __half& hi, __half& lo) {
    hi = __float2half(v);
    lo = __float2half(v - __half2float(hi));
}

// ---------------------------------------------------------------------------
// LayerNorm -> g_q (fp16 hi only)
// ---------------------------------------------------------------------------
__global__ void __launch_bounds__(256) ln_kernel(const float* __restrict__ res,
                                                 const float* __restrict__ gam,
                                                 const float* __restrict__ bet) {
    const int row = blockIdx.x;
    const float* x = res + (size_t)row * C_;
    const int t = threadIdx.x;

    float v[4];
    float s = 0.f;
#pragma unroll
    for (int i = 0; i < 4; i++) { v[i] = x[t + 256 * i]; s += v[i]; }

    __shared__ float red[8];
    __shared__ float sh_mu, sh_rs;
#pragma unroll
    for (int o = 16; o; o >>= 1) s += __shfl_xor_sync(0xffffffffu, s, o);
    if ((t & 31) == 0) red[t >> 5] = s;
    __syncthreads();
    if (t == 0) {
        float tot = 0.f;
#pragma unroll
        for (int i = 0; i < 8; i++) tot += red[i];
        sh_mu = tot * (1.0f / (float)C_);
    }
    __syncthreads();
    const float mu = sh_mu;
    float s2 = 0.f;
#pragma unroll
    for (int i = 0; i < 4; i++) { float d = v[i] - mu; s2 += d * d; }
#pragma unroll
    for (int o = 16; o; o >>= 1) s2 += __shfl_xor_sync(0xffffffffu, s2, o);
    if ((t & 31) == 0) red[t >> 5] = s2;
    __syncthreads();
    if (t == 0) {
        float tot = 0.f;
#pragma unroll
        for (int i = 0; i < 8; i++) tot += red[i];
        sh_rs = rsqrtf(tot * (1.0f / (float)C_) + EPS_);
    }
    __syncthreads();
    const float rs = sh_rs;

#pragma unroll
    for (int i = 0; i < 4; i++) {
        int c = t + 256 * i;
        float y = (v[i] - mu) * rs * gam[c] + bet[c];
        g_q[(size_t)row * 1024 + c] = __float2half(y);
    }
}

__global__ void __launch_bounds__(256) kext_kernel(const float* __restrict__ wfc) {
    int idx = blockIdx.x * 256 + threadIdx.x;
    float v = wfc[idx];
    int s = idx >> 8, d = idx & 255;
    __half hi, lo;
    fp16_split(v, hi, lo);
    g_k[(size_t)s * 512 + d] = hi;
    g_k[(size_t)s * 512 + 256 + d] = lo;
}

__global__ void __launch_bounds__(256) vext_kernel(const float* __restrict__ wproj) {
    int idx = blockIdx.x * 256 + threadIdx.x;
    float v = wproj[idx];
    int r = idx >> 10, cc = idx & 1023;
    int d = r & 255;
    int s = cc * 4 + (r >> 8);
    __half hi, lo;
    fp16_split(v, hi, lo);
    g_vt[(size_t)d * 4096 + s] = hi;
    g_vt[1048576ull + (size_t)d * 4096 + s] = lo;
}

// ---------------------------------------------------------------------------
// Reduce: out = residual + sum of 4 partials
// ---------------------------------------------------------------------------
__global__ void __launch_bounds__(256) reduce_kernel(const float* __restrict__ res,
                                                     float* __restrict__ out) {
    const size_t i = ((size_t)blockIdx.x * 256 + threadIdx.x) * 4;
    float4 a = *(const float4*)(res + i);
    float4 p0 = *(const float4*)(g_part + i);
    float4 p1 = *(const float4*)(g_part + (size_t)BT_ * C_ + i);
    float4 p2 = *(const float4*)(g_part + 2ull * BT_ * C_ + i);
    float4 p3 = *(const float4*)(g_part + 3ull * BT_ * C_ + i);
    float4 o;
    o.x = a.x + (p0.x + p1.x) + (p2.x + p3.x);
    o.y = a.y + (p0.y + p1.y) + (p2.y + p3.y);
    o.z = a.z + (p0.z + p1.z) + (p2.z + p3.z);
    o.w = a.w + (p0.w + p1.w) + (p2.w + p3.w);
    *(float4*)(out + i) = o;
}

// ---------------------------------------------------------------------------
// Fused kernel: CTA = 128 rows x 1 head x 1 S-split(1024); S chunks of 64.
// fp16; GEMM1 2 terms (Q unsplit, K split); GEMM2 2 terms (P unsplit, V split).
// GEMM1 warp tile 32m x 32s (4x2). GEMM2 warp tile 64m x 64d (2x4).
// SMEM: Q[128][528], P[128][144], K[64][1040], V 2sl x [256][144].
// ---------------------------------------------------------------------------
#define SQ_OFF   0            // 128*528    = 67584
#define SP_OFF   67584        // 128*144    = 18432
#define SK_OFF   86016        // 64*1040    = 66560
#define SV_OFF   152576       // 2*256*144  = 73728
#define SV_LO    36864
#define SMEM_TOT 226304
#define NIT      (SSEG / 64)  // 16 chunks per split

__global__ void __launch_bounds__(256, 1) fused_kernel() {
    extern __shared__ char smem[];
    const uint32_t sb = smem_u32(smem);

    const int t = threadIdx.x;
    const int lane = t & 31;
    const int wid = t >> 5;
    const int r = lane >> 2;        // 0..7
    const int u = lane & 3;         // 0..3
    const int head = blockIdx.y;
    const int row0 = blockIdx.x * 128;
    const int sBase = blockIdx.z * SSEG;

    // GEMM1 warp coords: 4 m-groups x 2 s-halves(32 each)
    const int my = wid & 3;
    const int sx = wid >> 2;
    // GEMM2 warp coords: 2 m-halves x 4 d-quarters
    const int mh = wid & 1;
    const int dq = wid >> 1;

    // ---- issue Q (group), K(0) (group), V(0) (group) ----
#pragma unroll
    for (int i = 0; i < 16; i++) {
        int idx = i * 256 + t;
        int m = idx >> 5, c = idx & 31;
        CPA16(sb + SQ_OFF + m * 528 + c * 16,
              (const void*)(g_q + (size_t)(row0 + m) * 1024 + head * 256 + c * 8));
    }
    CPCOMMIT();
#pragma unroll
    for (int i = 0; i < 16; i++) {
        int idx = i * 256 + t;
        int s = idx >> 6, c = idx & 63;
        CPA16(sb + SK_OFF + s * 1040 + c * 16,
              (const void*)(g_k + (size_t)(sBase + s) * 512 + c * 8));
    }
    CPCOMMIT();
#pragma unroll
    for (int i = 0; i < 16; i++) {
        int idx = i * 256 + t;
        int hilo = idx >> 11;
        int rem = idx & 2047;
        int d = rem >> 3, c = rem & 7;
        CPA16(sb + SV_OFF + hilo * SV_LO + d * 144 + c * 16,
              (const void*)(g_vt + (size_t)hilo * 1048576ull + (size_t)d * 4096 + sBase + c * 8));
    }
    CPCOMMIT();
    CPWAIT(1);              // Q + K(0) complete; V(0) pending
    __syncthreads();

    // ldmatrix lane addressing
    const uint32_t qa = sb + SQ_OFF + (uint32_t)((my * 32 + (lane & 15)) * 528 + (lane >> 4) * 16);
    const int brow = (lane & 7) + ((lane >> 4) << 3);
    const int bc8  = ((lane >> 3) & 1) << 3;
    const uint32_t kb = sb + SK_OFF + (uint32_t)((sx * 32 + brow) * 1040 + bc8 * 2);
    const uint32_t pa = sb + SP_OFF + (uint32_t)((mh * 64 + (lane & 15)) * 144 + (lane >> 4) * 16);
    const uint32_t vb = sb + SV_OFF + (uint32_t)((dq * 64 + brow) * 144 + bc8 * 2);
    const uint32_t pw = sb + SP_OFF + (uint32_t)((my * 32 + r) * 144 + (sx * 32 + 2 * u) * 2);

    float c2[4][8][4];
#pragma unroll
    for (int a = 0; a < 4; a++)
#pragma unroll
        for (int b = 0; b < 8; b++)
#pragma unroll
            for (int e = 0; e < 4; e++) c2[a][b][e] = 0.f;

    for (int it = 0; it < NIT; it++) {
        // ---- GEMM1: scores[128 x 64]  (K(it) visible) ----
        float c1[2][4][4];
#pragma unroll
        for (int a = 0; a < 2; a++)
#pragma unroll
            for (int b = 0; b < 4; b++)
#pragma unroll
                for (int e = 0; e < 4; e++) c1[a][b][e] = 0.f;

#pragma unroll 8
        for (int ks = 0; ks < 16; ks++) {
            uint32_t a0[4], a1[4], bh0[4], bh1[4], bl0[4], bl1[4];
            ldsm4(a0, qa + ks * 32);
            ldsm4(a1, qa + 16 * 528 + ks * 32);
            ldsm4(bh0, kb + ks * 32);
            ldsm4(bh1, kb + 16 * 1040 + ks * 32);
            ldsm4(bl0, kb + 512 + ks * 32);
            ldsm4(bl1, kb + 16 * 1040 + 512 + ks * 32);
            mma16816(c1[0][0], a0, bh0);  mma16816(c1[0][1], a0, bh0 + 2);
            mma16816(c1[0][2], a0, bh1);  mma16816(c1[0][3], a0, bh1 + 2);
            mma16816(c1[1][0], a1, bh0);  mma16816(c1[1][1], a1, bh0 + 2);
            mma16816(c1[1][2], a1, bh1);  mma16816(c1[1][3], a1, bh1 + 2);
            mma16816(c1[0][0], a0, bl0);  mma16816(c1[0][1], a0, bl0 + 2);
            mma16816(c1[0][2], a0, bl1);  mma16816(c1[0][3], a0, bl1 + 2);
            mma16816(c1[1][0], a1, bl0);  mma16816(c1[1][1], a1, bl0 + 2);
            mma16816(c1[1][2], a1, bl1);  mma16816(c1[1][3], a1, bl1 + 2);
        }
        __syncthreads();        // sync_a: K buffer free

        // issue K(it+1)
        if (it < NIT - 1) {
            const int sn = sBase + (it + 1) * 64;
#pragma unroll
            for (int i = 0; i < 16; i++) {
                int idx = i * 256 + t;
                int s = idx >> 6, c = idx & 63;
                CPA16(sb + SK_OFF + s * 1040 + c * 16,
                      (const void*)(g_k + (size_t)(sn + s) * 512 + c * 8));
            }
            CPCOMMIT();
        }

        // ---- relu^2 -> P (unsplit fp16) smem (overlaps K load) ----
#pragma unroll
        for (int mt = 0; mt < 2; mt++) {
#pragma unroll
            for (int nt = 0; nt < 4; nt++) {
                uint32_t base = pw + (uint32_t)(mt * 16 * 144 + nt * 16);
#pragma unroll
                for (int half = 0; half < 2; half++) {
                    float p0 = fmaxf(c1[mt][nt][half * 2], 0.f);
                    float p1 = fmaxf(c1[mt][nt][half * 2 + 1], 0.f);
                    uint32_t a = base + half * (8 * 144);
                    *(uint32_t*)(smem + (a - sb)) = pack_h2(p0 * p0, p1 * p1);
                }
            }
        }

        if (it < NIT - 1) { CPWAIT(1); } else { CPWAIT(0); }   // V(it) complete
        __syncthreads();        // sync_b: P + V visible

        // ---- GEMM2: O[128 x 256] += P . (Vh + Vl)^T  (2 terms) ----
#pragma unroll
        for (int ks = 0; ks < 4; ks++) {
            uint32_t Ph[4][4];
#pragma unroll
            for (int mt = 0; mt < 4; mt++)
                ldsm4(Ph[mt], pa + (uint32_t)(mt * 16 * 144 + ks * 32));
#pragma unroll
            for (int h = 0; h < 4; h++) {
                uint32_t vh[4], vl[4];
                ldsm4(vh, vb + (uint32_t)(h * 16 * 144 + ks * 32));
                ldsm4(vl, vb + (uint32_t)(SV_LO + h * 16 * 144 + ks * 32));
#pragma unroll
                for (int mt = 0; mt < 4; mt++) {
                    float* cA = c2[mt][2 * h];
                    float* cB = c2[mt][2 * h + 1];
                    mma16816(cA, Ph[mt], vh);  mma16816(cB, Ph[mt], vh + 2);
                    mma16816(cA, Ph[mt], vl);  mma16816(cB, Ph[mt], vl + 2);
                }
            }
        }

        CPWAIT(0);              // K(it+1) complete
        __syncthreads();        // sync_c: V,P free; K visible

        // issue V(it+1)
        if (it < NIT - 1) {
            const int sv = sBase + (it + 1) * 64;
#pragma unroll
            for (int i = 0; i < 16; i++) {
                int idx = i * 256 + t;
                int hilo = idx >> 11;
                int rem = idx & 2047;
                int d = rem >> 3, c = rem & 7;
                CPA16(sb + SV_OFF + hilo * SV_LO + d * 144 + c * 16,
                      (const void*)(g_vt + (size_t)hilo * 1048576ull +
                                    (size_t)d * 4096 + sv + c * 8));
            }
            CPCOMMIT();
        }
    }

    // ---- epilogue: write partial O (no residual) ----
    float* po = g_part + (size_t)blockIdx.z * BT_ * C_;
#pragma unroll
    for (int mt = 0; mt < 4; mt++) {
        const int rowA = row0 + mh * 64 + mt * 16 + r;
        const int rowB = rowA + 8;
        float* oA = po + (size_t)rowA * C_ + head * 256;
        float* oB = po + (size_t)rowB * C_ + head * 256;
#pragma unroll
        for (int j = 0; j < 8; j++) {
            const int col = dq * 64 + (j >> 1) * 16 + (j & 1) * 8 + 2 * u;
            *(float2*)(oA + col) = make_float2(c2[mt][j][0], c2[mt][j][1]);
            *(float2*)(oB + col) = make_float2(c2[mt][j][2], c2[mt][j][3]);
        }
    }
}

// ---------------------------------------------------------------------------
extern "C" void kernel_launch(void* const* d_in, const int* in_sizes, int n_in,
                              void* d_out, int out_size) {
    (void)in_sizes; (void)n_in; (void)out_size;
    const float* residual = (const float*)d_in[0];
    const float* w_fc     = (const float*)d_in[1];
    const float* w_proj   = (const float*)d_in[2];
    const float* ln_g     = (const float*)d_in[3];
    const float* ln_b     = (const float*)d_in[4];
    float* out = (float*)d_out;

    cudaFuncSetAttribute(fused_kernel, cudaFuncAttributeMaxDynamicSharedMemorySize,
                         SMEM_TOT);

    ln_kernel<<<BT_, 256>>>(residual, ln_g, ln_b);
    kext_kernel<<<4096, 256>>>(w_fc);
    vext_kernel<<<4096, 256>>>(w_proj);
    fused_kernel<<<dim3(64, QH_, NSPLIT), 256, SMEM_TOT>>>();
    reduce_kernel<<<BT_ * C_ / 1024, 256>>>(residual, out);
}

// round 14
// speedup vs baseline: 2.6076x; 1.6274x over previous
#include <cuda_runtime.h>
#include <cuda_fp16.h>
#include <cstdint>

#define BT_   8192
#define C_    1024
#define S_    4096
#define QH_   4
#define EPS_  1e-5f
#define NSPLIT 4
#define SSEG  1024            // S per split

// ---------------- scratch ----------------
__device__ __half g_q[(size_t)BT_ * 1024];   // 16MB [row][h*256 + d]
__device__ __half g_k[(size_t)S_ * 256];     //  2MB [s][d]
__device__ __half g_vt[256ull * S_];         //  2MB [d][s]
__device__ float g_part[(size_t)NSPLIT * BT_ * C_]; // 134MB partial outputs

// ---------------- helpers ----------------
__device__ __forceinline__ uint32_t smem_u32(const void* p) {
    uint32_t a;
    asm("{ .reg .u64 t; cvta.to.shared.u64 t, %1; cvt.u32.u64 %0, t; }" : "=r"(a) : "l"(p));
    return a;
}
#define CPA16(saddr, gptr) \
    asm volatile("cp.async.cg.shared.global [%0], [%1], 16;" :: "r"(saddr), "l"(gptr))
#define CPCOMMIT() asm volatile("cp.async.commit_group;" ::: "memory")
#define CPWAIT(n)  asm volatile("cp.async.wait_group " #n ";" ::: "memory")

__device__ __forceinline__ void ldsm4(uint32_t* r, uint32_t addr) {
    asm volatile("ldmatrix.sync.aligned.m8n8.x4.shared.b16 {%0,%1,%2,%3}, [%4];"
                 : "=r"(r[0]), "=r"(r[1]), "=r"(r[2]), "=r"(r[3]) : "r"(addr));
}
__device__ __forceinline__ void mma16816(float* c, const uint32_t* a, const uint32_t* b) {
    asm volatile("mma.sync.aligned.m16n8k16.row.col.f32.f16.f16.f32 "
                 "{%0,%1,%2,%3}, {%4,%5,%6,%7}, {%8,%9}, {%0,%1,%2,%3};"
                 : "+f"(c[0]), "+f"(c[1]), "+f"(c[2]), "+f"(c[3])
                 : "r"(a[0]), "r"(a[1]), "r"(a[2]), "r"(a[3]), "r"(b[0]), "r"(b[1]));
}
__device__ __forceinline__ uint32_t pack_h2(float f0, float f1) {
    __half2 h = __floats2half2_rn(f0, f1);
    return *reinterpret_cast<uint32_t*>(&h);
}

// ---------------------------------------------------------------------------
// LayerNorm -> g_q (fp16)
// ---------------------------------------------------------------------------
__global__ void __launch_bounds__(256) ln_kernel(const float* __restrict__ res,
                                                 const float* __restrict__ gam,
                                                 const float* __restrict__ bet) {
    const int row = blockIdx.x;
    const float* x = res + (size_t)row * C_;
    const int t = threadIdx.x;

    float v[4];
    float s = 0.f;
#pragma unroll
    for (int i = 0; i < 4; i++) { v[i] = x[t + 256 * i]; s += v[i]; }

    __shared__ float red[8];
    __shared__ float sh_mu, sh_rs;
#pragma unroll
    for (int o = 16; o; o >>= 1) s += __shfl_xor_sync(0xffffffffu, s, o);
    if ((t & 31) == 0) red[t >> 5] = s;
    __syncthreads();
    if (t == 0) {
        float tot = 0.f;
#pragma unroll
        for (int i = 0; i < 8; i++) tot += red[i];
        sh_mu = tot * (1.0f / (float)C_);
    }
    __syncthreads();
    const float mu = sh_mu;
    float s2 = 0.f;
#pragma unroll
    for (int i = 0; i < 4; i++) { float d = v[i] - mu; s2 += d * d; }
#pragma unroll
    for (int o = 16; o; o >>= 1) s2 += __shfl_xor_sync(0xffffffffu, s2, o);
    if ((t & 31) == 0) red[t >> 5] = s2;
    __syncthreads();
    if (t == 0) {
        float tot = 0.f;
#pragma unroll
        for (int i = 0; i < 8; i++) tot += red[i];
        sh_rs = rsqrtf(tot * (1.0f / (float)C_) + EPS_);
    }
    __syncthreads();
    const float rs = sh_rs;

#pragma unroll
    for (int i = 0; i < 4; i++) {
        int c = t + 256 * i;
        float y = (v[i] - mu) * rs * gam[c] + bet[c];
        g_q[(size_t)row * 1024 + c] = __float2half(y);
    }
}

__global__ void __launch_bounds__(256) kext_kernel(const float* __restrict__ wfc) {
    int idx = blockIdx.x * 256 + threadIdx.x;
    g_k[idx] = __float2half(wfc[idx]);
}

__global__ void __launch_bounds__(256) vext_kernel(const float* __restrict__ wproj) {
    int idx = blockIdx.x * 256 + threadIdx.x;
    float v = wproj[idx];
    int r = idx >> 10, cc = idx & 1023;
    int d = r & 255;
    int s = cc * 4 + (r >> 8);
    g_vt[(size_t)d * 4096 + s] = __float2half(v);
}

// ---------------------------------------------------------------------------
// Reduce: out = residual + sum of 4 partials
// ---------------------------------------------------------------------------
__global__ void __launch_bounds__(256) reduce_kernel(const float* __restrict__ res,
                                                     float* __restrict__ out) {
    const size_t i = ((size_t)blockIdx.x * 256 + threadIdx.x) * 4;
    float4 a = *(const float4*)(res + i);
    float4 p0 = *(const float4*)(g_part + i);
    float4 p1 = *(const float4*)(g_part + (size_t)BT_ * C_ + i);
    float4 p2 = *(const float4*)(g_part + 2ull * BT_ * C_ + i);
    float4 p3 = *(const float4*)(g_part + 3ull * BT_ * C_ + i);
    float4 o;
    o.x = a.x + (p0.x + p1.x) + (p2.x + p3.x);
    o.y = a.y + (p0.y + p1.y) + (p2.y + p3.y);
    o.z = a.z + (p0.z + p1.z) + (p2.z + p3.z);
    o.w = a.w + (p0.w + p1.w) + (p2.w + p3.w);
    *(float4*)(out + i) = o;
}

// ---------------------------------------------------------------------------
// Fused kernel: CTA = 128 rows x 1 head x 1 S-split(1024); S chunks of 64.
// Pure fp16 operands (no splits). K and V double-buffered; 2 barriers/chunk.
// GEMM1 warp tile 32m x 32s (4x2). GEMM2 warp tile 64m x 64d (2x4).
// SMEM: Q[128][528B], P[128][144B], K 2x[64][528B], V 2x[256][144B] = 227328B.
// ---------------------------------------------------------------------------
#define SQ_OFF   0            // 128*528    = 67584
#define SP_OFF   67584        // 128*144    = 18432
#define SK_OFF   86016        // 2 x 64*528  = 67584
#define SK_SZ    33792
#define SV_OFF   153600       // 2 x 256*144 = 73728
#define SV_SZ    36864
#define SMEM_TOT 227328
#define NIT      (SSEG / 64)  // 16 chunks per split

__global__ void __launch_bounds__(256, 1) fused_kernel() {
    extern __shared__ char smem[];
    const uint32_t sb = smem_u32(smem);

    const int t = threadIdx.x;
    const int lane = t & 31;
    const int wid = t >> 5;
    const int r = lane >> 2;        // 0..7
    const int u = lane & 3;         // 0..3
    const int head = blockIdx.y;
    const int row0 = blockIdx.x * 128;
    const int sBase = blockIdx.z * SSEG;

    // GEMM1 warp coords: 4 m-groups x 2 s-halves(32 each)
    const int my = wid & 3;
    const int sx = wid >> 2;
    // GEMM2 warp coords: 2 m-halves x 4 d-quarters
    const int mh = wid & 1;
    const int dq = wid >> 1;

    // ---- prologue: issue Q + K(0) + V(0) as one group ----
#pragma unroll
    for (int i = 0; i < 16; i++) {
        int idx = i * 256 + t;
        int m = idx >> 5, c = idx & 31;
        CPA16(sb + SQ_OFF + m * 528 + c * 16,
              (const void*)(g_q + (size_t)(row0 + m) * 1024 + head * 256 + c * 8));
    }
#pragma unroll
    for (int i = 0; i < 8; i++) {
        int idx = i * 256 + t;
        int s = idx >> 5, c = idx & 31;
        CPA16(sb + SK_OFF + s * 528 + c * 16,
              (const void*)(g_k + (size_t)(sBase + s) * 256 + c * 8));
    }
#pragma unroll
    for (int i = 0; i < 8; i++) {
        int idx = i * 256 + t;
        int d = idx >> 3, c = idx & 7;
        CPA16(sb + SV_OFF + d * 144 + c * 16,
              (const void*)(g_vt + (size_t)d * 4096 + sBase + c * 8));
    }
    CPCOMMIT();
    CPWAIT(0);
    __syncthreads();

    // ldmatrix lane addressing
    const uint32_t qa = sb + SQ_OFF + (uint32_t)((my * 32 + (lane & 15)) * 528 + (lane >> 4) * 16);
    const int brow = (lane & 7) + ((lane >> 4) << 3);
    const int bc8  = ((lane >> 3) & 1) << 3;
    const uint32_t kb0 = sb + SK_OFF + (uint32_t)((sx * 32 + brow) * 528 + bc8 * 2);
    const uint32_t pa = sb + SP_OFF + (uint32_t)((mh * 64 + (lane & 15)) * 144 + (lane >> 4) * 16);
    const uint32_t vb0 = sb + SV_OFF + (uint32_t)((dq * 64 + brow) * 144 + bc8 * 2);
    const uint32_t pw = sb + SP_OFF + (uint32_t)((my * 32 + r) * 144 + (sx * 32 + 2 * u) * 2);

    float c2[4][8][4];
#pragma unroll
    for (int a = 0; a < 4; a++)
#pragma unroll
        for (int b = 0; b < 8; b++)
#pragma unroll
            for (int e = 0; e < 4; e++) c2[a][b][e] = 0.f;

    for (int it = 0; it < NIT; it++) {
        const int buf = it & 1;
        const uint32_t kb = kb0 + buf * SK_SZ;
        const uint32_t vb = vb0 + buf * SV_SZ;

        // issue K(it+1) + V(it+1) into the other buffers (flies under both GEMMs)
        if (it < NIT - 1) {
            const int sn = sBase + (it + 1) * 64;
            const uint32_t ko = sb + SK_OFF + (buf ^ 1) * SK_SZ;
            const uint32_t vo = sb + SV_OFF + (buf ^ 1) * SV_SZ;
#pragma unroll
            for (int i = 0; i < 8; i++) {
                int idx = i * 256 + t;
                int s = idx >> 5, c = idx & 31;
                CPA16(ko + s * 528 + c * 16,
                      (const void*)(g_k + (size_t)(sn + s) * 256 + c * 8));
            }
#pragma unroll
            for (int i = 0; i < 8; i++) {
                int idx = i * 256 + t;
                int d = idx >> 3, c = idx & 7;
                CPA16(vo + d * 144 + c * 16,
                      (const void*)(g_vt + (size_t)d * 4096 + sn + c * 8));
            }
            CPCOMMIT();
        }

        // ---- GEMM1: scores[128 x 64] ----
        float c1[2][4][4];
#pragma unroll
        for (int a = 0; a < 2; a++)
#pragma unroll
            for (int b = 0; b < 4; b++)
#pragma unroll
                for (int e = 0; e < 4; e++) c1[a][b][e] = 0.f;

#pragma unroll 8
        for (int ks = 0; ks < 16; ks++) {
            uint32_t a0[4], a1[4], b0[4], b1[4];
            ldsm4(a0, qa + ks * 32);
            ldsm4(a1, qa + 16 * 528 + ks * 32);
            ldsm4(b0, kb + ks * 32);
            ldsm4(b1, kb + 16 * 528 + ks * 32);
            mma16816(c1[0][0], a0, b0);  mma16816(c1[0][1], a0, b0 + 2);
            mma16816(c1[0][2], a0, b1);  mma16816(c1[0][3], a0, b1 + 2);
            mma16816(c1[1][0], a1, b0);  mma16816(c1[1][1], a1, b0 + 2);
            mma16816(c1[1][2], a1, b1);  mma16816(c1[1][3], a1, b1 + 2);
        }

        // ---- relu^2 -> P (fp16) smem ----
#pragma unroll
        for (int mt = 0; mt < 2; mt++) {
#pragma unroll
            for (int nt = 0; nt < 4; nt++) {
                uint32_t base = pw + (uint32_t)(mt * 16 * 144 + nt * 16);
#pragma unroll
                for (int half = 0; half < 2; half++) {
                    float p0 = fmaxf(c1[mt][nt][half * 2], 0.f);
                    float p1 = fmaxf(c1[mt][nt][half * 2 + 1], 0.f);
                    uint32_t a = base + half * (8 * 144);
                    *(uint32_t*)(smem + (a - sb)) = pack_h2(p0 * p0, p1 * p1);
                }
            }
        }
        __syncthreads();        // sync_mid: P visible to all warps

        // ---- GEMM2: O[128 x 256] += P . V^T ----
#pragma unroll
        for (int ks = 0; ks < 4; ks++) {
            uint32_t Ph[4][4];
#pragma unroll
            for (int mt = 0; mt < 4; mt++)
                ldsm4(Ph[mt], pa + (uint32_t)(mt * 16 * 144 + ks * 32));
#pragma unroll
            for (int h = 0; h < 4; h++) {
                uint32_t vh[4];
                ldsm4(vh, vb + (uint32_t)(h * 16 * 144 + ks * 32));
#pragma unroll
                for (int mt = 0; mt < 4; mt++) {
                    mma16816(c2[mt][2 * h],     Ph[mt], vh);
                    mma16816(c2[mt][2 * h + 1], Ph[mt], vh + 2);
                }
            }
        }

        if (it < NIT - 1) CPWAIT(0);   // K(it+1)+V(it+1) landed
        __syncthreads();               // sync_end: P free; next buffers visible
    }

    // ---- epilogue: write partial O (no residual) ----
    float* po = g_part + (size_t)blockIdx.z * BT_ * C_;
#pragma unroll
    for (int mt = 0; mt < 4; mt++) {
        const int rowA = row0 + mh * 64 + mt * 16 + r;
        const int rowB = rowA + 8;
        float* oA = po + (size_t)rowA * C_ + head * 256;
        float* oB = po + (size_t)rowB * C_ + head * 256;
#pragma unroll
        for (int j = 0; j < 8; j++) {
            const int col = dq * 64 + (j >> 1) * 16 + (j & 1) * 8 + 2 * u;
            *(float2*)(oA + col) = make_float2(c2[mt][j][0], c2[mt][j][1]);
            *(float2*)(oB + col) = make_float2(c2[mt][j][2], c2[mt][j][3]);
        }
    }
}

// ---------------------------------------------------------------------------
extern "C" void kernel_launch(void* const* d_in, const int* in_sizes, int n_in,
                              void* d_out, int out_size) {
    (void)in_sizes; (void)n_in; (void)out_size;
    const float* residual = (const float*)d_in[0];
    const float* w_fc     = (const float*)d_in[1];
    const float* w_proj   = (const float*)d_in[2];
    const float* ln_g     = (const float*)d_in[3];
    const float* ln_b     = (const float*)d_in[4];
    float* out = (float*)d_out;

    cudaFuncSetAttribute(fused_kernel, cudaFuncAttributeMaxDynamicSharedMemorySize,
                         SMEM_TOT);

    ln_kernel<<<BT_, 256>>>(residual, ln_g, ln_b);
    kext_kernel<<<4096, 256>>>(w_fc);
    vext_kernel<<<4096, 256>>>(w_proj);
    fused_kernel<<<dim3(64, QH_, NSPLIT), 256, SMEM_TOT>>>();
    reduce_kernel<<<BT_ * C_ / 1024, 256>>>(residual, out);
}